// round 1
// baseline (speedup 1.0000x reference)
#include <cuda_runtime.h>
#include <cstdint>

// Problem constants
#define B_      2048
#define OBS_    512
#define DMODEL  1024
#define DSTATE  16
#define DCONV   4
#define DINNER  2048          // EXPAND * DMODEL
#define DTRANK  64            // (1024+15)//16
#define XDB_N   96            // DTRANK + 2*DSTATE
#define ACT_    18

// ---------------- scratch (static device globals; no allocation) ----------
__device__ float g_h    [(size_t)B_ * DMODEL];        // 8 MB
__device__ float g_xz   [(size_t)B_ * 2 * DINNER];    // 32 MB
__device__ float g_xconv[(size_t)B_ * DINNER];        // 16 MB
__device__ float g_xdb  [(size_t)B_ * XDB_N];         // 0.75 MB
__device__ float g_dt   [(size_t)B_ * DINNER];        // 16 MB
__device__ float g_y    [(size_t)B_ * DINNER];        // 16 MB
__device__ float g_out  [(size_t)B_ * DMODEL];        // 8 MB
__device__ float g_negA [(size_t)DINNER * DSTATE];    // 128 KB

// ---------------- generic fp32 SGEMM: C[M,N] = A[M,K] * W[N,K]^T ----------
// EPI: 0 = none, 1 = +bias, 2 = softplus(x + bias)
#define BM 128
#define BN 128
#define BKK 16

template <int EPI>
__global__ void __launch_bounds__(256)
sgemm_kernel(const float* __restrict__ A, int lda,
             const float* __restrict__ W, int ldw,
             const float* __restrict__ bias,
             float* __restrict__ C, int ldc,
             int N, int K)
{
    __shared__ float As[BKK][BM];
    __shared__ float Bs[BKK][BN];

    const int tid = threadIdx.x;
    const int m0 = blockIdx.y * BM;
    const int n0 = blockIdx.x * BN;
    const int tx = tid & 15;          // 0..15 -> N direction
    const int ty = tid >> 4;          // 0..15 -> M direction

    float acc[8][8];
    #pragma unroll
    for (int i = 0; i < 8; i++)
        #pragma unroll
        for (int j = 0; j < 8; j++) acc[i][j] = 0.f;

    for (int k0 = 0; k0 < K; k0 += BKK) {
        // A tile: 128 rows x 16 cols = 512 float4 loads (2 per thread)
        #pragma unroll
        for (int i = 0; i < 2; i++) {
            int f   = tid + i * 256;
            int row = f >> 2;
            int c4  = (f & 3) * 4;
            float4 v = *reinterpret_cast<const float4*>(
                &A[(size_t)(m0 + row) * lda + k0 + c4]);
            As[c4 + 0][row] = v.x; As[c4 + 1][row] = v.y;
            As[c4 + 2][row] = v.z; As[c4 + 3][row] = v.w;
        }
        // W tile: 128 rows (n) x 16 cols (k); guard n < N
        #pragma unroll
        for (int i = 0; i < 2; i++) {
            int f   = tid + i * 256;
            int row = f >> 2;
            int c4  = (f & 3) * 4;
            float4 v = make_float4(0.f, 0.f, 0.f, 0.f);
            if (n0 + row < N)
                v = *reinterpret_cast<const float4*>(
                    &W[(size_t)(n0 + row) * ldw + k0 + c4]);
            Bs[c4 + 0][row] = v.x; Bs[c4 + 1][row] = v.y;
            Bs[c4 + 2][row] = v.z; Bs[c4 + 3][row] = v.w;
        }
        __syncthreads();

        #pragma unroll
        for (int k = 0; k < BKK; k++) {
            float a[8], bb[8];
            float4 a0 = *reinterpret_cast<const float4*>(&As[k][ty * 8]);
            float4 a1 = *reinterpret_cast<const float4*>(&As[k][ty * 8 + 4]);
            float4 b0 = *reinterpret_cast<const float4*>(&Bs[k][tx * 8]);
            float4 b1 = *reinterpret_cast<const float4*>(&Bs[k][tx * 8 + 4]);
            a[0]=a0.x; a[1]=a0.y; a[2]=a0.z; a[3]=a0.w;
            a[4]=a1.x; a[5]=a1.y; a[6]=a1.z; a[7]=a1.w;
            bb[0]=b0.x; bb[1]=b0.y; bb[2]=b0.z; bb[3]=b0.w;
            bb[4]=b1.x; bb[5]=b1.y; bb[6]=b1.z; bb[7]=b1.w;
            #pragma unroll
            for (int i = 0; i < 8; i++)
                #pragma unroll
                for (int j = 0; j < 8; j++)
                    acc[i][j] = fmaf(a[i], bb[j], acc[i][j]);
        }
        __syncthreads();
    }

    #pragma unroll
    for (int i = 0; i < 8; i++) {
        int m = m0 + ty * 8 + i;
        #pragma unroll
        for (int j = 0; j < 8; j++) {
            int n = n0 + tx * 8 + j;
            if (n < N) {
                float v = acc[i][j];
                if (EPI >= 1) v += bias[n];
                if (EPI == 2) v = (v > 20.f) ? v : log1pf(expf(v));
                C[(size_t)m * ldc + n] = v;
            }
        }
    }
}

// ---------------- negA = -exp(A_log) --------------------------------------
__global__ void nega_kernel(const float* __restrict__ A_log)
{
    int i = blockIdx.x * blockDim.x + threadIdx.x;
    if (i < DINNER * DSTATE) g_negA[i] = -expf(A_log[i]);
}

// ---------------- conv: shift state, depthwise conv, silu -----------------
__global__ void __launch_bounds__(256)
conv_kernel(const float* __restrict__ conv_state,
            const float* __restrict__ conv_w,
            const float* __restrict__ conv_b,
            float* __restrict__ conv_out)  // d_out conv_state_new region
{
    int idx = blockIdx.x * blockDim.x + threadIdx.x;   // b*DINNER + d
    int d = idx & (DINNER - 1);
    int b = idx >> 11;

    float4 cs = reinterpret_cast<const float4*>(conv_state)[idx];
    float xv  = g_xz[((size_t)b << 12) + d];           // xz[b, d]
    float4 nw = make_float4(cs.y, cs.z, cs.w, xv);
    float4 w  = reinterpret_cast<const float4*>(conv_w)[d];
    float acc = nw.x * w.x + nw.y * w.y + nw.z * w.z + nw.w * w.w + conv_b[d];

    reinterpret_cast<float4*>(conv_out)[idx] = nw;
    g_xconv[idx] = acc / (1.f + __expf(-acc));         // silu
}

// ---------------- SSM state update + C-reduction + gating -----------------
__global__ void __launch_bounds__(256)
ssm_kernel(const float* __restrict__ ssm_state,
           const float* __restrict__ Dvec,
           float* __restrict__ ssm_out)   // d_out ssm_state_new region
{
    __shared__ float sBC[32];            // B (16) then C (16) for this batch row
    int idx = blockIdx.x * blockDim.x + threadIdx.x;   // b*DINNER + d
    int d = idx & (DINNER - 1);
    int b = idx >> 11;

    if (threadIdx.x < 32)
        sBC[threadIdx.x] = g_xdb[(size_t)b * XDB_N + DTRANK + threadIdx.x];
    __syncthreads();

    float dt = g_dt[idx];
    float x  = g_xconv[idx];
    float z  = g_xz[((size_t)b << 12) + DINNER + d];
    float xdt = x * dt;

    const float4* sOld = reinterpret_cast<const float4*>(ssm_state) + (size_t)idx * 4;
    float4*       sNew = reinterpret_cast<float4*>(ssm_out) + (size_t)idx * 4;
    const float*  nA   = &g_negA[d * DSTATE];

    float y = 0.f;
    #pragma unroll
    for (int q = 0; q < 4; q++) {
        float4 so = sOld[q];
        float4 sn;
        int n = q * 4;
        sn.x = so.x * __expf(dt * nA[n + 0]) + xdt * sBC[n + 0];
        sn.y = so.y * __expf(dt * nA[n + 1]) + xdt * sBC[n + 1];
        sn.z = so.z * __expf(dt * nA[n + 2]) + xdt * sBC[n + 2];
        sn.w = so.w * __expf(dt * nA[n + 3]) + xdt * sBC[n + 3];
        sNew[q] = sn;
        y = fmaf(sn.x, sBC[16 + n + 0], y);
        y = fmaf(sn.y, sBC[16 + n + 1], y);
        y = fmaf(sn.z, sBC[16 + n + 2], y);
        y = fmaf(sn.w, sBC[16 + n + 3], y);
    }
    y += Dvec[d] * x;
    g_y[idx] = y * (z / (1.f + __expf(-z)));           // * silu(z)
}

// ---------------- policy/value heads: out[b,:] @ {pol_w,val_w}^T ----------
__global__ void __launch_bounds__(256)
head_kernel(const float* __restrict__ pol_w, const float* __restrict__ pol_b,
            const float* __restrict__ val_w, const float* __restrict__ val_b,
            float* __restrict__ logits, float* __restrict__ value)
{
    __shared__ float row[DMODEL];
    int b = blockIdx.x;
    for (int k = threadIdx.x; k < DMODEL; k += 256)
        row[k] = g_out[(size_t)b * DMODEL + k];
    __syncthreads();

    int warp = threadIdx.x >> 5;
    int lane = threadIdx.x & 31;
    for (int j = warp; j < ACT_ + 1; j += 8) {
        const float* w = (j < ACT_) ? &pol_w[(size_t)j * DMODEL] : val_w;
        float s = 0.f;
        for (int k = lane; k < DMODEL; k += 32)
            s = fmaf(row[k], w[k], s);
        #pragma unroll
        for (int o = 16; o > 0; o >>= 1)
            s += __shfl_down_sync(0xffffffffu, s, o);
        if (lane == 0) {
            if (j < ACT_) logits[(size_t)b * ACT_ + j] = s + pol_b[j];
            else          value[b] = s + val_b[0];
        }
    }
}

// ---------------- launch ---------------------------------------------------
extern "C" void kernel_launch(void* const* d_in, const int* in_sizes, int n_in,
                              void* d_out, int out_size)
{
    const float* obs        = (const float*)d_in[0];
    const float* conv_state = (const float*)d_in[1];
    const float* ssm_state  = (const float*)d_in[2];
    const float* in_proj_w  = (const float*)d_in[3];
    const float* in_proj_b  = (const float*)d_in[4];
    const float* mamba_in_w = (const float*)d_in[5];
    const float* conv_w     = (const float*)d_in[6];
    const float* conv_b     = (const float*)d_in[7];
    const float* x_proj_w   = (const float*)d_in[8];
    const float* dt_w       = (const float*)d_in[9];
    const float* dt_b       = (const float*)d_in[10];
    const float* A_log      = (const float*)d_in[11];
    const float* Dvec       = (const float*)d_in[12];
    const float* out_proj_w = (const float*)d_in[13];
    const float* pol_w      = (const float*)d_in[14];
    const float* pol_b      = (const float*)d_in[15];
    const float* val_w      = (const float*)d_in[16];
    const float* val_b      = (const float*)d_in[17];

    float* out      = (float*)d_out;
    float* logits   = out;                                  // [B, 18]
    float* value    = logits + (size_t)B_ * ACT_;           // [B, 1]
    float* conv_out = value + B_;                           // [B, DINNER, 4]
    float* ssm_out  = conv_out + (size_t)B_ * DINNER * DCONV; // [B, DINNER, 16]

    float *p_h, *p_xz, *p_xconv, *p_xdb, *p_dt, *p_y, *p_out;
    cudaGetSymbolAddress((void**)&p_h,     g_h);
    cudaGetSymbolAddress((void**)&p_xz,    g_xz);
    cudaGetSymbolAddress((void**)&p_xconv, g_xconv);
    cudaGetSymbolAddress((void**)&p_xdb,   g_xdb);
    cudaGetSymbolAddress((void**)&p_dt,    g_dt);
    cudaGetSymbolAddress((void**)&p_y,     g_y);
    cudaGetSymbolAddress((void**)&p_out,   g_out);

    // A = -exp(A_log) (independent of pipeline; launch first)
    nega_kernel<<<(DINNER * DSTATE + 255) / 256, 256>>>(A_log);

    // 1) h = obs @ in_proj_w^T + in_proj_b        [2048 x 1024], K=512
    sgemm_kernel<1><<<dim3(DMODEL / BN, B_ / BM), 256>>>(
        obs, OBS_, in_proj_w, OBS_, in_proj_b, p_h, DMODEL, DMODEL, OBS_);

    // 2) xz = h @ mamba_in_w^T                    [2048 x 4096], K=1024
    sgemm_kernel<0><<<dim3(2 * DINNER / BN, B_ / BM), 256>>>(
        p_h, DMODEL, mamba_in_w, DMODEL, nullptr, p_xz, 2 * DINNER,
        2 * DINNER, DMODEL);

    // 3) conv shift + depthwise conv + silu
    conv_kernel<<<(B_ * DINNER) / 256, 256>>>(conv_state, conv_w, conv_b, conv_out);

    // 4) x_db = xconv @ x_proj_w^T                [2048 x 96], K=2048
    sgemm_kernel<0><<<dim3(1, B_ / BM), 256>>>(
        p_xconv, DINNER, x_proj_w, DINNER, nullptr, p_xdb, XDB_N, XDB_N, DINNER);

    // 5) dt = softplus(x_db[:, :64] @ dt_w^T + dt_b)   [2048 x 2048], K=64
    sgemm_kernel<2><<<dim3(DINNER / BN, B_ / BM), 256>>>(
        p_xdb, XDB_N, dt_w, DTRANK, dt_b, p_dt, DINNER, DINNER, DTRANK);

    // 6) SSM state update + y reduction + gate
    ssm_kernel<<<(B_ * DINNER) / 256, 256>>>(ssm_state, Dvec, ssm_out);

    // 7) out = y @ out_proj_w^T                   [2048 x 1024], K=2048
    sgemm_kernel<0><<<dim3(DMODEL / BN, B_ / BM), 256>>>(
        p_y, DINNER, out_proj_w, DINNER, nullptr, p_out, DMODEL, DMODEL, DINNER);

    // 8) heads
    head_kernel<<<B_, 256>>>(pol_w, pol_b, val_w, val_b, logits, value);

    (void)in_sizes; (void)n_in; (void)out_size;
}

// round 2
// speedup vs baseline: 1.5488x; 1.5488x over previous
#include <cuda_runtime.h>
#include <cuda_bf16.h>
#include <cstdint>

// Problem constants
#define B_      2048
#define OBS_    512
#define DMODEL  1024
#define DSTATE  16
#define DCONV   4
#define DINNER  2048          // EXPAND * DMODEL
#define DTRANK  64            // (1024+15)//16
#define XDB_N   96            // DTRANK + 2*DSTATE
#define ACT_    18

// ---------------- scratch (static device globals; no allocation) ----------
__device__ float g_h    [(size_t)B_ * DMODEL];
__device__ float g_xz   [(size_t)B_ * 2 * DINNER];
__device__ float g_xconv[(size_t)B_ * DINNER];
__device__ float g_xdb  [(size_t)B_ * XDB_N];
__device__ float g_dt   [(size_t)B_ * DINNER];
__device__ float g_y    [(size_t)B_ * DINNER];
__device__ float g_out  [(size_t)B_ * DMODEL];
__device__ float g_negA [(size_t)DINNER * DSTATE];

// ===========================================================================
// Split-bf16 tensor-core GEMM:  C[M,N] = A[M,K] @ W[N,K]^T   (fp32 in/out)
// Each fp32 value v is split as v = hi + lo (both bf16). Product uses
// hi*hi + lo*hi + hi*lo (drops lo*lo, ~2^-18 relative) -> ~1e-5 accuracy.
// Tile: BM=128, BN=128, BK=32. 256 threads = 8 warps in 4(m) x 2(n) grid;
// warp tile 32x64 via m16n8k16 mma.sync.
// EPI: 0 = none, 1 = +bias, 2 = softplus(x + bias)
// Requires: M % 128 == 0, N % 128 == 0, K % 32 == 0, rows 16B-aligned.
// ===========================================================================

#define SLD 40   // smem row stride in bf16 elems (80B: conflict-free ldmatrix)

__device__ __forceinline__ uint32_t smem_u32(const void* p) {
    return (uint32_t)__cvta_generic_to_shared(p);
}

__device__ __forceinline__ void ldm_x4(uint32_t r[4], const __nv_bfloat16* p) {
    asm volatile("ldmatrix.sync.aligned.m8n8.x4.shared.b16 {%0,%1,%2,%3}, [%4];"
                 : "=r"(r[0]), "=r"(r[1]), "=r"(r[2]), "=r"(r[3])
                 : "r"(smem_u32(p)));
}

__device__ __forceinline__ void mma_bf16(float c[4], const uint32_t a[4],
                                         const uint32_t b0, const uint32_t b1) {
    asm volatile(
        "mma.sync.aligned.m16n8k16.row.col.f32.bf16.bf16.f32 "
        "{%0,%1,%2,%3}, {%4,%5,%6,%7}, {%8,%9}, {%0,%1,%2,%3};"
        : "+f"(c[0]), "+f"(c[1]), "+f"(c[2]), "+f"(c[3])
        : "r"(a[0]), "r"(a[1]), "r"(a[2]), "r"(a[3]), "r"(b0), "r"(b1));
}

__device__ __forceinline__ void split_store(__nv_bfloat16* ph, __nv_bfloat16* pl,
                                            float4 v) {
    __nv_bfloat16 h0 = __float2bfloat16(v.x);
    __nv_bfloat16 h1 = __float2bfloat16(v.y);
    __nv_bfloat16 h2 = __float2bfloat16(v.z);
    __nv_bfloat16 h3 = __float2bfloat16(v.w);
    __nv_bfloat16 l0 = __float2bfloat16(v.x - __bfloat162float(h0));
    __nv_bfloat16 l1 = __float2bfloat16(v.y - __bfloat162float(h1));
    __nv_bfloat16 l2 = __float2bfloat16(v.z - __bfloat162float(h2));
    __nv_bfloat16 l3 = __float2bfloat16(v.w - __bfloat162float(h3));
    *reinterpret_cast<__nv_bfloat162*>(ph + 0) = __nv_bfloat162(h0, h1);
    *reinterpret_cast<__nv_bfloat162*>(ph + 2) = __nv_bfloat162(h2, h3);
    *reinterpret_cast<__nv_bfloat162*>(pl + 0) = __nv_bfloat162(l0, l1);
    *reinterpret_cast<__nv_bfloat162*>(pl + 2) = __nv_bfloat162(l2, l3);
}

template <int EPI>
__global__ void __launch_bounds__(256, 2)
bmma_kernel(const float* __restrict__ A, int lda,
            const float* __restrict__ W, int ldw,
            const float* __restrict__ bias,
            float* __restrict__ C, int ldc, int K)
{
    __shared__ __nv_bfloat16 Ah[128 * SLD], Al[128 * SLD];
    __shared__ __nv_bfloat16 Bh[128 * SLD], Bl[128 * SLD];

    const int tid  = threadIdx.x;
    const int warp = tid >> 5;
    const int lane = tid & 31;
    const int m0 = blockIdx.y * 128;
    const int n0 = blockIdx.x * 128;
    const int wm = (warp >> 1) * 32;   // warp m offset in tile
    const int wn = (warp & 1) * 64;    // warp n offset in tile

    // ldmatrix per-lane addressing
    const int a_r = lane & 15;               // row within 16-row frag
    const int a_c = (lane >> 4) << 3;        // k offset 0/8
    const int b_r = ((lane >> 4) << 3) + (lane & 7);  // row within 16-n pair
    const int b_c = ((lane >> 3) & 1) << 3;  // k offset 0/8

    float c[2][8][4];
    #pragma unroll
    for (int i = 0; i < 2; i++)
        #pragma unroll
        for (int j = 0; j < 8; j++)
            #pragma unroll
            for (int q = 0; q < 4; q++) c[i][j][q] = 0.f;

    for (int k0 = 0; k0 < K; k0 += 32) {
        // ---- load + split 128x32 fp32 tiles of A and W into smem ----
        #pragma unroll
        for (int i = 0; i < 4; i++) {
            int idx = tid + i * 256;        // 0..1023
            int row = idx >> 3;             // 0..127
            int col = (idx & 7) * 4;        // 0..28
            float4 va = *reinterpret_cast<const float4*>(
                &A[(size_t)(m0 + row) * lda + k0 + col]);
            float4 vb = *reinterpret_cast<const float4*>(
                &W[(size_t)(n0 + row) * ldw + k0 + col]);
            split_store(&Ah[row * SLD + col], &Al[row * SLD + col], va);
            split_store(&Bh[row * SLD + col], &Bl[row * SLD + col], vb);
        }
        __syncthreads();

        #pragma unroll
        for (int kk = 0; kk < 32; kk += 16) {
            uint32_t ah[2][4], al[2][4];
            #pragma unroll
            for (int mf = 0; mf < 2; mf++) {
                ldm_x4(ah[mf], &Ah[(wm + mf * 16 + a_r) * SLD + kk + a_c]);
                ldm_x4(al[mf], &Al[(wm + mf * 16 + a_r) * SLD + kk + a_c]);
            }
            // process 8 n-frags in two halves of 4 to bound registers
            #pragma unroll
            for (int h = 0; h < 2; h++) {
                uint32_t bh[4][2], bl[4][2];
                #pragma unroll
                for (int p = 0; p < 2; p++) {   // each x4 covers 2 n-frags
                    uint32_t r[4];
                    ldm_x4(r, &Bh[(wn + (h * 4 + p * 2) * 8 + b_r) * SLD + kk + b_c]);
                    bh[p * 2][0] = r[0]; bh[p * 2][1] = r[1];
                    bh[p * 2 + 1][0] = r[2]; bh[p * 2 + 1][1] = r[3];
                }
                #pragma unroll
                for (int f = 0; f < 4; f++) {
                    int nf = h * 4 + f;
                    mma_bf16(c[0][nf], ah[0], bh[f][0], bh[f][1]);
                    mma_bf16(c[1][nf], ah[1], bh[f][0], bh[f][1]);
                    mma_bf16(c[0][nf], al[0], bh[f][0], bh[f][1]);
                    mma_bf16(c[1][nf], al[1], bh[f][0], bh[f][1]);
                }
                #pragma unroll
                for (int p = 0; p < 2; p++) {
                    uint32_t r[4];
                    ldm_x4(r, &Bl[(wn + (h * 4 + p * 2) * 8 + b_r) * SLD + kk + b_c]);
                    bl[p * 2][0] = r[0]; bl[p * 2][1] = r[1];
                    bl[p * 2 + 1][0] = r[2]; bl[p * 2 + 1][1] = r[3];
                }
                #pragma unroll
                for (int f = 0; f < 4; f++) {
                    int nf = h * 4 + f;
                    mma_bf16(c[0][nf], ah[0], bl[f][0], bl[f][1]);
                    mma_bf16(c[1][nf], ah[1], bl[f][0], bl[f][1]);
                }
            }
        }
        __syncthreads();
    }

    // ---- epilogue ----
    const int cr = lane >> 2;          // 0..7
    const int cc = (lane & 3) * 2;     // 0,2,4,6
    #pragma unroll
    for (int mf = 0; mf < 2; mf++) {
        #pragma unroll
        for (int nf = 0; nf < 8; nf++) {
            int m = m0 + wm + mf * 16 + cr;
            int n = n0 + wn + nf * 8 + cc;
            float v0 = c[mf][nf][0], v1 = c[mf][nf][1];
            float v2 = c[mf][nf][2], v3 = c[mf][nf][3];
            if (EPI >= 1) {
                float b0 = bias[n], b1 = bias[n + 1];
                v0 += b0; v1 += b1; v2 += b0; v3 += b1;
            }
            if (EPI == 2) {
                v0 = (v0 > 20.f) ? v0 : log1pf(expf(v0));
                v1 = (v1 > 20.f) ? v1 : log1pf(expf(v1));
                v2 = (v2 > 20.f) ? v2 : log1pf(expf(v2));
                v3 = (v3 > 20.f) ? v3 : log1pf(expf(v3));
            }
            *reinterpret_cast<float2*>(&C[(size_t)m * ldc + n]) =
                make_float2(v0, v1);
            *reinterpret_cast<float2*>(&C[(size_t)(m + 8) * ldc + n]) =
                make_float2(v2, v3);
        }
    }
}

// ---------------- fp32 SGEMM (kept for x_proj, N=96) ----------------------
#define BM 128
#define BN 128
#define BKK 16

__global__ void __launch_bounds__(256)
sgemm_kernel(const float* __restrict__ A, int lda,
             const float* __restrict__ W, int ldw,
             float* __restrict__ C, int ldc,
             int N, int K)
{
    __shared__ float As[BKK][BM];
    __shared__ float Bs[BKK][BN];

    const int tid = threadIdx.x;
    const int m0 = blockIdx.y * BM;
    const int n0 = blockIdx.x * BN;
    const int tx = tid & 15;
    const int ty = tid >> 4;

    float acc[8][8];
    #pragma unroll
    for (int i = 0; i < 8; i++)
        #pragma unroll
        for (int j = 0; j < 8; j++) acc[i][j] = 0.f;

    for (int k0 = 0; k0 < K; k0 += BKK) {
        #pragma unroll
        for (int i = 0; i < 2; i++) {
            int f   = tid + i * 256;
            int row = f >> 2;
            int c4  = (f & 3) * 4;
            float4 v = *reinterpret_cast<const float4*>(
                &A[(size_t)(m0 + row) * lda + k0 + c4]);
            As[c4 + 0][row] = v.x; As[c4 + 1][row] = v.y;
            As[c4 + 2][row] = v.z; As[c4 + 3][row] = v.w;
        }
        #pragma unroll
        for (int i = 0; i < 2; i++) {
            int f   = tid + i * 256;
            int row = f >> 2;
            int c4  = (f & 3) * 4;
            float4 v = make_float4(0.f, 0.f, 0.f, 0.f);
            if (n0 + row < N)
                v = *reinterpret_cast<const float4*>(
                    &W[(size_t)(n0 + row) * ldw + k0 + c4]);
            Bs[c4 + 0][row] = v.x; Bs[c4 + 1][row] = v.y;
            Bs[c4 + 2][row] = v.z; Bs[c4 + 3][row] = v.w;
        }
        __syncthreads();

        #pragma unroll
        for (int k = 0; k < BKK; k++) {
            float a[8], bb[8];
            float4 a0 = *reinterpret_cast<const float4*>(&As[k][ty * 8]);
            float4 a1 = *reinterpret_cast<const float4*>(&As[k][ty * 8 + 4]);
            float4 b0 = *reinterpret_cast<const float4*>(&Bs[k][tx * 8]);
            float4 b1 = *reinterpret_cast<const float4*>(&Bs[k][tx * 8 + 4]);
            a[0]=a0.x; a[1]=a0.y; a[2]=a0.z; a[3]=a0.w;
            a[4]=a1.x; a[5]=a1.y; a[6]=a1.z; a[7]=a1.w;
            bb[0]=b0.x; bb[1]=b0.y; bb[2]=b0.z; bb[3]=b0.w;
            bb[4]=b1.x; bb[5]=b1.y; bb[6]=b1.z; bb[7]=b1.w;
            #pragma unroll
            for (int i = 0; i < 8; i++)
                #pragma unroll
                for (int j = 0; j < 8; j++)
                    acc[i][j] = fmaf(a[i], bb[j], acc[i][j]);
        }
        __syncthreads();
    }

    #pragma unroll
    for (int i = 0; i < 8; i++) {
        int m = m0 + ty * 8 + i;
        #pragma unroll
        for (int j = 0; j < 8; j++) {
            int n = n0 + tx * 8 + j;
            if (n < N) C[(size_t)m * ldc + n] = acc[i][j];
        }
    }
}

// ---------------- negA = -exp(A_log) --------------------------------------
__global__ void nega_kernel(const float* __restrict__ A_log)
{
    int i = blockIdx.x * blockDim.x + threadIdx.x;
    if (i < DINNER * DSTATE) g_negA[i] = -expf(A_log[i]);
}

// ---------------- conv: shift state, depthwise conv, silu -----------------
__global__ void __launch_bounds__(256)
conv_kernel(const float* __restrict__ conv_state,
            const float* __restrict__ conv_w,
            const float* __restrict__ conv_b,
            float* __restrict__ conv_out)
{
    int idx = blockIdx.x * blockDim.x + threadIdx.x;   // b*DINNER + d
    int d = idx & (DINNER - 1);
    int b = idx >> 11;

    float4 cs = reinterpret_cast<const float4*>(conv_state)[idx];
    float xv  = g_xz[((size_t)b << 12) + d];
    float4 nw = make_float4(cs.y, cs.z, cs.w, xv);
    float4 w  = reinterpret_cast<const float4*>(conv_w)[d];
    float acc = nw.x * w.x + nw.y * w.y + nw.z * w.z + nw.w * w.w + conv_b[d];

    reinterpret_cast<float4*>(conv_out)[idx] = nw;
    g_xconv[idx] = acc / (1.f + __expf(-acc));
}

// ---------------- SSM state update + C-reduction + gating -----------------
__global__ void __launch_bounds__(256)
ssm_kernel(const float* __restrict__ ssm_state,
           const float* __restrict__ Dvec,
           float* __restrict__ ssm_out)
{
    __shared__ float sBC[32];
    int idx = blockIdx.x * blockDim.x + threadIdx.x;
    int d = idx & (DINNER - 1);
    int b = idx >> 11;

    if (threadIdx.x < 32)
        sBC[threadIdx.x] = g_xdb[(size_t)b * XDB_N + DTRANK + threadIdx.x];
    __syncthreads();

    float dt = g_dt[idx];
    float x  = g_xconv[idx];
    float z  = g_xz[((size_t)b << 12) + DINNER + d];
    float xdt = x * dt;

    const float4* sOld = reinterpret_cast<const float4*>(ssm_state) + (size_t)idx * 4;
    float4*       sNew = reinterpret_cast<float4*>(ssm_out) + (size_t)idx * 4;
    const float*  nA   = &g_negA[d * DSTATE];

    float y = 0.f;
    #pragma unroll
    for (int q = 0; q < 4; q++) {
        float4 so = sOld[q];
        float4 sn;
        int n = q * 4;
        sn.x = so.x * __expf(dt * nA[n + 0]) + xdt * sBC[n + 0];
        sn.y = so.y * __expf(dt * nA[n + 1]) + xdt * sBC[n + 1];
        sn.z = so.z * __expf(dt * nA[n + 2]) + xdt * sBC[n + 2];
        sn.w = so.w * __expf(dt * nA[n + 3]) + xdt * sBC[n + 3];
        sNew[q] = sn;
        y = fmaf(sn.x, sBC[16 + n + 0], y);
        y = fmaf(sn.y, sBC[16 + n + 1], y);
        y = fmaf(sn.z, sBC[16 + n + 2], y);
        y = fmaf(sn.w, sBC[16 + n + 3], y);
    }
    y += Dvec[d] * x;
    g_y[idx] = y * (z / (1.f + __expf(-z)));
}

// ---------------- policy/value heads ---------------------------------------
__global__ void __launch_bounds__(256)
head_kernel(const float* __restrict__ pol_w, const float* __restrict__ pol_b,
            const float* __restrict__ val_w, const float* __restrict__ val_b,
            float* __restrict__ logits, float* __restrict__ value)
{
    __shared__ float row[DMODEL];
    int b = blockIdx.x;
    for (int k = threadIdx.x; k < DMODEL; k += 256)
        row[k] = g_out[(size_t)b * DMODEL + k];
    __syncthreads();

    int warp = threadIdx.x >> 5;
    int lane = threadIdx.x & 31;
    for (int j = warp; j < ACT_ + 1; j += 8) {
        const float* w = (j < ACT_) ? &pol_w[(size_t)j * DMODEL] : val_w;
        float s = 0.f;
        for (int k = lane; k < DMODEL; k += 32)
            s = fmaf(row[k], w[k], s);
        #pragma unroll
        for (int o = 16; o > 0; o >>= 1)
            s += __shfl_down_sync(0xffffffffu, s, o);
        if (lane == 0) {
            if (j < ACT_) logits[(size_t)b * ACT_ + j] = s + pol_b[j];
            else          value[b] = s + val_b[0];
        }
    }
}

// ---------------- launch ---------------------------------------------------
extern "C" void kernel_launch(void* const* d_in, const int* in_sizes, int n_in,
                              void* d_out, int out_size)
{
    const float* obs        = (const float*)d_in[0];
    const float* conv_state = (const float*)d_in[1];
    const float* ssm_state  = (const float*)d_in[2];
    const float* in_proj_w  = (const float*)d_in[3];
    const float* in_proj_b  = (const float*)d_in[4];
    const float* mamba_in_w = (const float*)d_in[5];
    const float* conv_w     = (const float*)d_in[6];
    const float* conv_b     = (const float*)d_in[7];
    const float* x_proj_w   = (const float*)d_in[8];
    const float* dt_w       = (const float*)d_in[9];
    const float* dt_b       = (const float*)d_in[10];
    const float* A_log      = (const float*)d_in[11];
    const float* Dvec       = (const float*)d_in[12];
    const float* out_proj_w = (const float*)d_in[13];
    const float* pol_w      = (const float*)d_in[14];
    const float* pol_b      = (const float*)d_in[15];
    const float* val_w      = (const float*)d_in[16];
    const float* val_b      = (const float*)d_in[17];

    float* out      = (float*)d_out;
    float* logits   = out;
    float* value    = logits + (size_t)B_ * ACT_;
    float* conv_out = value + B_;
    float* ssm_out  = conv_out + (size_t)B_ * DINNER * DCONV;

    float *p_h, *p_xz, *p_xconv, *p_xdb, *p_dt, *p_y, *p_out;
    cudaGetSymbolAddress((void**)&p_h,     g_h);
    cudaGetSymbolAddress((void**)&p_xz,    g_xz);
    cudaGetSymbolAddress((void**)&p_xconv, g_xconv);
    cudaGetSymbolAddress((void**)&p_xdb,   g_xdb);
    cudaGetSymbolAddress((void**)&p_dt,    g_dt);
    cudaGetSymbolAddress((void**)&p_y,     g_y);
    cudaGetSymbolAddress((void**)&p_out,   g_out);

    nega_kernel<<<(DINNER * DSTATE + 255) / 256, 256>>>(A_log);

    // 1) h = obs @ in_proj_w^T + b   [2048 x 1024], K=512  (tensor)
    bmma_kernel<1><<<dim3(DMODEL / 128, B_ / 128), 256>>>(
        obs, OBS_, in_proj_w, OBS_, in_proj_b, p_h, DMODEL, OBS_);

    // 2) xz = h @ mamba_in_w^T       [2048 x 4096], K=1024 (tensor)
    bmma_kernel<0><<<dim3(2 * DINNER / 128, B_ / 128), 256>>>(
        p_h, DMODEL, mamba_in_w, DMODEL, nullptr, p_xz, 2 * DINNER, DMODEL);

    // 3) conv shift + depthwise conv + silu
    conv_kernel<<<(B_ * DINNER) / 256, 256>>>(conv_state, conv_w, conv_b, conv_out);

    // 4) x_db = xconv @ x_proj_w^T   [2048 x 96], K=2048  (fp32; N=96)
    sgemm_kernel<<<dim3(1, B_ / BM), 256>>>(
        p_xconv, DINNER, x_proj_w, DINNER, p_xdb, XDB_N, XDB_N, DINNER);

    // 5) dt = softplus(x_db[:, :64] @ dt_w^T + dt_b)  [2048 x 2048], K=64 (tensor)
    bmma_kernel<2><<<dim3(DINNER / 128, B_ / 128), 256>>>(
        p_xdb, XDB_N, dt_w, DTRANK, dt_b, p_dt, DINNER, DTRANK);

    // 6) SSM state update + y reduction + gate
    ssm_kernel<<<(B_ * DINNER) / 256, 256>>>(ssm_state, Dvec, ssm_out);

    // 7) out = y @ out_proj_w^T      [2048 x 1024], K=2048 (tensor)
    bmma_kernel<0><<<dim3(DMODEL / 128, B_ / 128), 256>>>(
        p_y, DINNER, out_proj_w, DINNER, nullptr, p_out, DMODEL, DINNER);

    // 8) heads
    head_kernel<<<B_, 256>>>(pol_w, pol_b, val_w, val_b, logits, value);

    (void)in_sizes; (void)n_in; (void)out_size;
}